// round 12
// baseline (speedup 1.0000x reference)
#include <cuda_runtime.h>
#include <cuda_bf16.h>
#include <cstdint>

// Problem constants (fixed by the dataset): B=64, T=12, C=64, SIDE=32, S2=1024.
#define PB   64
#define PT   12
#define PC   64
#define PS2  1024
#define ROWS (PB * PC)          // 4096 (b,c) rows in the last-T slice

#define GRID   592              // 148 SMs x 4 blocks/SM EXACTLY => balanced + co-resident
#define RPBMAX 7                // 544 blocks take 7 rows, 48 take 6 (4096 total)
#define FULL7  544
#define NSHARD 8                // global mask atomic shards
#define NCTR   16               // arrival counter shards (592/16 = 37)

// Persistent scratch (module-load zeroed; last block restores zeros each launch
// => every call identical => graph-replay deterministic).
__device__ unsigned g_maskpad[NSHARD * 32 * 64];  // word (k,i) at (k*32+i)*64: 256B stride
__device__ int      g_cnt[NCTR * 64];             // padded arrival counters
__device__ int      g_master;
__device__ volatile int g_flag;                   // dedicated spin line
__device__ int      g_c1;                         // epilogue counter

__global__ void __launch_bounds__(256, 4)
fused_kernel(const float* __restrict__ d, const int* __restrict__ m,
             const int* __restrict__ poi_words, float* __restrict__ out) {
    __shared__ float    rs[RPBMAX][PS2];  // 28 KB staged d rows
    __shared__ unsigned smask[32];        // block-partial 1024-bit mask
    __shared__ unsigned smw[32];          // combined mask words (phase 2)
    __shared__ int      sh_odd, sh_last;

    const int t = threadIdx.x;            // 0..255
    const int g = blockIdx.x;             // 0..591
    const int start = 7 * g - max(0, g - FULL7);
    const int cnt   = (g < FULL7) ? 7 : 6;

    if (t == 0) { sh_odd = 0; sh_last = 0; }
    if (t < 32) smask[t] = 0;

    // ---- per-row bases (rows may cross the b boundary) ----
    size_t base[RPBMAX];
#pragma unroll
    for (int r = 0; r < RPBMAX; r++) {
        const int R = start + r;
        const int b = R >> 6, c = R & 63;
        base[r] = ((size_t)(b * PT + (PT - 1)) * PC + c) * PS2;
    }

    // ---- issue ALL global loads up front (m rows, poi, d rows) ----
    int4 acc = make_int4(0, 0, 0, 0);
#pragma unroll
    for (int r = 0; r < RPBMAX; r++) {
        if (r < cnt) {
            const int4 v = *(const int4*)(m + base[r] + 4 * t);
            acc.x |= v.x; acc.y |= v.y; acc.z |= v.z; acc.w |= v.w;
        }
    }

    // poi: every block decodes it (dtype auto-detect; JAX silently narrows
    // jnp.int64 -> int32). Read first 1024 words (safe for both dtypes) for
    // the int32 interpretation + detection; int64 lo-words at 2i.
    const int4 w  = ((const int4*)poi_words)[t];
    const int4 p0 = ((const int4*)poi_words)[2 * t];
    const int4 p1 = ((const int4*)poi_words)[2 * t + 1];
    if (w.y | w.w) atomicOr(&sh_odd, 1);

    float4 v[RPBMAX];
#pragma unroll
    for (int r = 0; r < RPBMAX; r++)
        if (r < cnt) v[r] = *(const float4*)(d + base[r] + 4 * t);
#pragma unroll
    for (int r = 0; r < RPBMAX; r++)
        if (r < cnt) ((float4*)rs[r])[t] = v[r];

    __syncthreads();      // rs staged, sh_odd final, smask zeroed

    // thread's 4 poi indices (cells 4t..4t+3)
    const int4 pi = sh_odd ? w : make_int4(p0.x, p0.z, p1.x, p1.z);

    // block-partial mask
    const unsigned nib = (acc.x ? 1u : 0u) | (acc.y ? 2u : 0u)
                       | (acc.z ? 4u : 0u) | (acc.w ? 8u : 0u);
    if (nib) atomicOr(&smask[t >> 3], nib << ((t & 7) * 4));
    __syncthreads();      // smask final

    // sharded global mask flush, then ARRIVE (no spin yet)
    if (t < 32 && smask[t])
        atomicOr(&g_maskpad[(((g & (NSHARD - 1)) * 32 + t) << 6)], smask[t]);
    if (t == 0) {
        __threadfence();                               // release mask partials
        const int r = atomicAdd(&g_cnt[(g & (NCTR - 1)) << 6], 1);
        if (r == GRID / NCTR - 1) {
            const int rm = atomicAdd(&g_master, 1);
            if (rm == NCTR - 1) { __threadfence(); g_flag = 1; }
        }
    }

    // ---- speculative compensation gathers (LDS) — overlap the barrier ----
    float4 comp[RPBMAX];
#pragma unroll
    for (int r = 0; r < RPBMAX; r++) {
        if (r < cnt) {
            comp[r].x = rs[r][pi.x];
            comp[r].y = rs[r][pi.y];
            comp[r].z = rs[r][pi.z];
            comp[r].w = rs[r][pi.w];
        }
    }

    // ---- wait for global mask publication ----
    if (t == 0) {
        while (!g_flag) {
#if __CUDA_ARCH__ >= 700
            __nanosleep(64);
#endif
        }
    }
    __syncthreads();
    __threadfence();                                   // acquire

    // ---- phase 2: combine shards, predicated add, store ----
    if (t < 32) {
        unsigned x = 0;
#pragma unroll
        for (int k = 0; k < NSHARD; k++)
            x |= ((volatile unsigned*)g_maskpad)[((k * 32 + t) << 6)];
        smw[t] = x;
    }
    __syncthreads();
    const unsigned nib2 = (smw[t >> 3] >> ((t & 7) * 4)) & 0xFu;  // 1 = nonzero cell

#pragma unroll
    for (int r = 0; r < RPBMAX; r++) {
        if (r < cnt) {
            float4 x = v[r];
            if (!(nib2 & 1u)) x.x += comp[r].x;
            if (!(nib2 & 2u)) x.y += comp[r].y;
            if (!(nib2 & 4u)) x.z += comp[r].z;
            if (!(nib2 & 8u)) x.w += comp[r].w;
            ((float4*)(out + (size_t)(start + r) * PS2))[t] = x;
        }
    }

    // ---- epilogue: last-arriving block resets all state (parallel) ----
    if (t == 0) {
        __threadfence();
        if (atomicAdd(&g_c1, 1) == GRID - 1) sh_last = 1;
    }
    __syncthreads();
    if (sh_last) {
        for (int i = t; i < NSHARD * 32; i += 256)
            g_maskpad[i << 6] = 0;
        if (t < NCTR) g_cnt[t << 6] = 0;
        if (t == 0) { g_master = 0; g_c1 = 0; g_flag = 0; __threadfence(); }
    }
}

extern "C" void kernel_launch(void* const* d_in, const int* in_sizes, int n_in,
                              void* d_out, int out_size) {
    const float* d   = (const float*)d_in[0];
    const int*   m   = (const int*)d_in[1];
    const int*   poi = (const int*)d_in[2];   // int32 or int64 words, auto-detected
    // d_in[3] = side (constant 32), unused.
    float* out = (float*)d_out;

    fused_kernel<<<GRID, 256>>>(d, m, poi, out);
}